// round 3
// baseline (speedup 1.0000x reference)
#include <cuda_runtime.h>
#include <cuda_bf16.h>
#include <cstdint>

// CBOW negative-sampling loss.
// Inputs (metadata order):
//  0: ctx_words    int32  [B,1]
//  1: target_words int32  [B,1]
//  2: neg_words    int32  [B,K]
//  3: V_emb        f32    [VOCAB,E]
//  4: U_emb        f32    [VOCAB,E]
//  5: mask_v       f32    [B,1,E]
//  6: mask_u       f32    [B,1,E]
//  7: mask_neg     f32    [B,K,E]
// Output: scalar f32 = -mean_b( logsig(pos_b) + logsig(negsum_b) )

#define E_DIM 128
#define K_NEG 10
#define THREADS 512          // 16 warps -> 16 batch rows per block
#define WARPS_PER_BLOCK (THREADS / 32)

__device__ __forceinline__ float log_sigmoid(float x) {
    // stable: min(x,0) - log1p(exp(-|x|))
    return fminf(x, 0.0f) - log1pf(expf(-fabsf(x)));
}

__global__ void __launch_bounds__(THREADS) cbow_zero(float* out) {
    if (threadIdx.x == 0 && blockIdx.x == 0) out[0] = 0.0f;
}

__global__ void __launch_bounds__(THREADS) cbow_loss_kernel(
    const int* __restrict__ ctx_words,
    const int* __restrict__ target_words,
    const int* __restrict__ neg_words,
    const float* __restrict__ V_emb,
    const float* __restrict__ U_emb,
    const float* __restrict__ mask_v,
    const float* __restrict__ mask_u,
    const float* __restrict__ mask_neg,
    float* __restrict__ out,
    int B, float neg_inv_B)
{
    const int lane = threadIdx.x & 31;
    const int warp_in_blk = threadIdx.x >> 5;
    const int b = blockIdx.x * WARPS_PER_BLOCK + warp_in_blk;

    float warp_loss = 0.0f;

    if (b < B) {
        // ---- v = V_emb[ctx[b]] * mask_v[b]  (lane owns 4 floats) ----
        const int c = ctx_words[b];
        float4 v4 = reinterpret_cast<const float4*>(V_emb + (size_t)c * E_DIM)[lane];
        {
            float4 m = reinterpret_cast<const float4*>(mask_v + (size_t)b * E_DIM)[lane];
            v4.x *= m.x; v4.y *= m.y; v4.z *= m.z; v4.w *= m.w;
        }

        // ---- pos = dot(U_emb[tgt[b]] * mask_u[b], v) ----
        const int t = target_words[b];
        float pos;
        {
            float4 u4 = reinterpret_cast<const float4*>(U_emb + (size_t)t * E_DIM)[lane];
            float4 m = reinterpret_cast<const float4*>(mask_u + (size_t)b * E_DIM)[lane];
            pos = u4.x * m.x * v4.x + u4.y * m.y * v4.y
                + u4.z * m.z * v4.z + u4.w * m.w * v4.w;
        }

        // ---- negsum = -sum_k dot(U_emb[neg[b,k]] * mask_neg[b,k], v) ----
        // Fully unrolled so ptxas front-batches all 20 float4 loads (MLP).
        int nidx[K_NEG];
        #pragma unroll
        for (int k = 0; k < K_NEG; ++k)
            nidx[k] = neg_words[(size_t)b * K_NEG + k];

        float negsum = 0.0f;
        #pragma unroll
        for (int k = 0; k < K_NEG; ++k) {
            float4 u4 = reinterpret_cast<const float4*>(
                U_emb + (size_t)nidx[k] * E_DIM)[lane];
            float4 m = reinterpret_cast<const float4*>(
                mask_neg + ((size_t)b * K_NEG + k) * E_DIM)[lane];
            negsum += u4.x * m.x * v4.x + u4.y * m.y * v4.y
                    + u4.z * m.z * v4.z + u4.w * m.w * v4.w;
        }
        negsum = -negsum;

        // ---- warp reductions (two values together) ----
        #pragma unroll
        for (int off = 16; off > 0; off >>= 1) {
            pos    += __shfl_xor_sync(0xFFFFFFFFu, pos, off);
            negsum += __shfl_xor_sync(0xFFFFFFFFu, negsum, off);
        }

        if (lane == 0)
            warp_loss = (log_sigmoid(pos) + log_sigmoid(negsum)) * neg_inv_B;
    }

    // ---- block reduction, one atomic per block ----
    __shared__ float sm[WARPS_PER_BLOCK];
    if (lane == 0) sm[warp_in_blk] = warp_loss;
    __syncthreads();
    if (threadIdx.x == 0) {
        float s = 0.0f;
        #pragma unroll
        for (int i = 0; i < WARPS_PER_BLOCK; ++i) s += sm[i];
        atomicAdd(out, s);
    }
}

extern "C" void kernel_launch(void* const* d_in, const int* in_sizes, int n_in,
                              void* d_out, int out_size)
{
    const int*   ctx      = (const int*)  d_in[0];
    const int*   tgt      = (const int*)  d_in[1];
    const int*   neg      = (const int*)  d_in[2];
    const float* V_emb    = (const float*)d_in[3];
    const float* U_emb    = (const float*)d_in[4];
    const float* mask_v   = (const float*)d_in[5];
    const float* mask_u   = (const float*)d_in[6];
    const float* mask_neg = (const float*)d_in[7];
    float* out = (float*)d_out;

    const int B = in_sizes[0];               // ctx_words has B*1 elements
    const float neg_inv_B = -1.0f / (float)B;

    cbow_zero<<<1, 32>>>(out);

    const int blocks = (B + WARPS_PER_BLOCK - 1) / WARPS_PER_BLOCK;
    cbow_loss_kernel<<<blocks, THREADS>>>(
        ctx, tgt, neg, V_emb, U_emb, mask_v, mask_u, mask_neg,
        out, B, neg_inv_B);
}

// round 5
// speedup vs baseline: 1.0970x; 1.0970x over previous
#include <cuda_runtime.h>
#include <cuda_bf16.h>
#include <cstdint>

// CBOW negative-sampling loss.
// Inputs (metadata order):
//  0: ctx_words    int32  [B,1]
//  1: target_words int32  [B,1]
//  2: neg_words    int32  [B,K]
//  3: V_emb        f32    [VOCAB,E]
//  4: U_emb        f32    [VOCAB,E]
//  5: mask_v       f32    [B,1,E]
//  6: mask_u       f32    [B,1,E]
//  7: mask_neg     f32    [B,K,E]
// Output: scalar f32 = -mean_b( logsig(pos_b) + logsig(negsum_b) )
//
// R4: sm_103a only allows L2 evict hints on 256-bit loads (.v8.b32) —
//     restructured so each lane owns 8 floats (16 lanes per row, warp
//     split into two half-warps; neg loop does 2 k's per iteration).
//     Tables -> evict_last (L2-resident ~102MB), masks -> evict_first
//     (read-once stream).

#define E_DIM 128
#define K_NEG 10
#define THREADS 512
#define WARPS_PER_BLOCK (THREADS / 32)

__device__ __forceinline__ float log_sigmoid(float x) {
    return fminf(x, 0.0f) - log1pf(expf(-fabsf(x)));
}

// 256-bit gather load (embedding tables): keep resident in L2.
__device__ __forceinline__ void ldg256_keep(const float* p, float r[8]) {
    asm("ld.global.nc.L2::evict_last.v8.b32 {%0,%1,%2,%3,%4,%5,%6,%7}, [%8];"
        : "=f"(r[0]), "=f"(r[1]), "=f"(r[2]), "=f"(r[3]),
          "=f"(r[4]), "=f"(r[5]), "=f"(r[6]), "=f"(r[7])
        : "l"(p));
}

// 256-bit streaming load (masks): read-once, evict first.
__device__ __forceinline__ void ldg256_stream(const float* p, float r[8]) {
    asm("ld.global.nc.L2::evict_first.v8.b32 {%0,%1,%2,%3,%4,%5,%6,%7}, [%8];"
        : "=f"(r[0]), "=f"(r[1]), "=f"(r[2]), "=f"(r[3]),
          "=f"(r[4]), "=f"(r[5]), "=f"(r[6]), "=f"(r[7])
        : "l"(p));
}

__global__ void __launch_bounds__(32) cbow_zero(float* out) {
    if (threadIdx.x == 0) out[0] = 0.0f;
}

__global__ void __launch_bounds__(THREADS) cbow_loss_kernel(
    const int* __restrict__ ctx_words,
    const int* __restrict__ target_words,
    const int* __restrict__ neg_words,
    const float* __restrict__ V_emb,
    const float* __restrict__ U_emb,
    const float* __restrict__ mask_v,
    const float* __restrict__ mask_u,
    const float* __restrict__ mask_neg,
    float* __restrict__ out,
    int B, float neg_inv_B)
{
    const int lane = threadIdx.x & 31;
    const int warp_in_blk = threadIdx.x >> 5;
    const int b = blockIdx.x * WARPS_PER_BLOCK + warp_in_blk;

    const int sub = lane & 15;   // 16 lanes cover one 128-float row (8 floats each)
    const int grp = lane >> 4;   // half-warp id: neg loop does k+grp

    float warp_loss = 0.0f;

    if (b < B) {
        const int foff = sub * 8;

        // ---- v = V_emb[ctx[b]] * mask_v[b] (duplicated across half-warps) ----
        const int c = ctx_words[b];
        float v[8], m[8];
        ldg256_keep(V_emb + (size_t)c * E_DIM + foff, v);
        ldg256_stream(mask_v + (size_t)b * E_DIM + foff, m);
        #pragma unroll
        for (int i = 0; i < 8; ++i) v[i] *= m[i];

        // ---- pos = dot(U_emb[tgt[b]] * mask_u[b], v)  (duplicated -> 2x) ----
        const int t = target_words[b];
        float u[8];
        ldg256_keep(U_emb + (size_t)t * E_DIM + foff, u);
        ldg256_stream(mask_u + (size_t)b * E_DIM + foff, m);
        float pos = 0.0f;
        #pragma unroll
        for (int i = 0; i < 8; ++i) pos += u[i] * m[i] * v[i];

        // ---- negsum: 2 k's per iteration (one per half-warp) ----
        float negsum = 0.0f;
        #pragma unroll
        for (int it = 0; it < K_NEG / 2; ++it) {
            const int k = 2 * it + grp;
            const int nidx = neg_words[(size_t)b * K_NEG + k];
            float un[8], mn[8];
            ldg256_keep(U_emb + (size_t)nidx * E_DIM + foff, un);
            ldg256_stream(mask_neg + ((size_t)b * K_NEG + k) * E_DIM + foff, mn);
            #pragma unroll
            for (int i = 0; i < 8; ++i) negsum += un[i] * mn[i] * v[i];
        }
        negsum = -negsum;

        // ---- warp reductions ----
        #pragma unroll
        for (int off = 16; off > 0; off >>= 1) {
            pos    += __shfl_xor_sync(0xFFFFFFFFu, pos, off);
            negsum += __shfl_xor_sync(0xFFFFFFFFu, negsum, off);
        }
        pos *= 0.5f;  // pos dot was computed by both half-warps

        if (lane == 0)
            warp_loss = (log_sigmoid(pos) + log_sigmoid(negsum)) * neg_inv_B;
    }

    // ---- block reduction, one atomic per block ----
    __shared__ float sm[WARPS_PER_BLOCK];
    if (lane == 0) sm[warp_in_blk] = warp_loss;
    __syncthreads();
    if (threadIdx.x == 0) {
        float s = 0.0f;
        #pragma unroll
        for (int i = 0; i < WARPS_PER_BLOCK; ++i) s += sm[i];
        atomicAdd(out, s);
    }
}

extern "C" void kernel_launch(void* const* d_in, const int* in_sizes, int n_in,
                              void* d_out, int out_size)
{
    const int*   ctx      = (const int*)  d_in[0];
    const int*   tgt      = (const int*)  d_in[1];
    const int*   neg      = (const int*)  d_in[2];
    const float* V_emb    = (const float*)d_in[3];
    const float* U_emb    = (const float*)d_in[4];
    const float* mask_v   = (const float*)d_in[5];
    const float* mask_u   = (const float*)d_in[6];
    const float* mask_neg = (const float*)d_in[7];
    float* out = (float*)d_out;

    const int B = in_sizes[0];
    const float neg_inv_B = -1.0f / (float)B;

    cbow_zero<<<1, 32>>>(out);

    const int blocks = (B + WARPS_PER_BLOCK - 1) / WARPS_PER_BLOCK;
    cbow_loss_kernel<<<blocks, THREADS>>>(
        ctx, tgt, neg, V_emb, U_emb, mask_v, mask_u, mask_neg,
        out, B, neg_inv_B);
}

// round 7
// speedup vs baseline: 1.2875x; 1.1737x over previous
#include <cuda_runtime.h>
#include <cuda_bf16.h>
#include <cstdint>

// CBOW negative-sampling loss.
// Inputs (metadata order):
//  0: ctx_words    int32  [B,1]
//  1: target_words int32  [B,1]
//  2: neg_words    int32  [B,K]
//  3: V_emb        f32    [VOCAB,E]
//  4: U_emb        f32    [VOCAB,E]
//  5: mask_v       f32    [B,1,E]
//  6: mask_u       f32    [B,1,E]
//  7: mask_neg     f32    [B,K,E]
// Output: scalar f32 = -mean_b( logsig(pos_b) + logsig(negsum_b) )
//
// R5: 256-thread blocks -> 5 blocks/SM at 44 regs (62.5% occ vs 47.9%),
//     restoring bytes-in-flight lost in R4. Neg indices hoisted ahead of
//     the fully-unrolled load loop for deeper front-batching.
//     (R4 win kept: 256-bit loads w/ L2 evict_last on tables,
//      evict_first on the read-once mask stream.)

#define E_DIM 128
#define K_NEG 10
#define THREADS 256
#define WARPS_PER_BLOCK (THREADS / 32)

__device__ __forceinline__ float log_sigmoid(float x) {
    return fminf(x, 0.0f) - log1pf(expf(-fabsf(x)));
}

// 256-bit gather load (embedding tables): keep resident in L2.
__device__ __forceinline__ void ldg256_keep(const float* p, float r[8]) {
    asm("ld.global.nc.L2::evict_last.v8.b32 {%0,%1,%2,%3,%4,%5,%6,%7}, [%8];"
        : "=f"(r[0]), "=f"(r[1]), "=f"(r[2]), "=f"(r[3]),
          "=f"(r[4]), "=f"(r[5]), "=f"(r[6]), "=f"(r[7])
        : "l"(p));
}

// 256-bit streaming load (masks): read-once, evict first.
__device__ __forceinline__ void ldg256_stream(const float* p, float r[8]) {
    asm("ld.global.nc.L2::evict_first.v8.b32 {%0,%1,%2,%3,%4,%5,%6,%7}, [%8];"
        : "=f"(r[0]), "=f"(r[1]), "=f"(r[2]), "=f"(r[3]),
          "=f"(r[4]), "=f"(r[5]), "=f"(r[6]), "=f"(r[7])
        : "l"(p));
}

__global__ void __launch_bounds__(32) cbow_zero(float* out) {
    if (threadIdx.x == 0) out[0] = 0.0f;
}

__global__ void __launch_bounds__(THREADS) cbow_loss_kernel(
    const int* __restrict__ ctx_words,
    const int* __restrict__ target_words,
    const int* __restrict__ neg_words,
    const float* __restrict__ V_emb,
    const float* __restrict__ U_emb,
    const float* __restrict__ mask_v,
    const float* __restrict__ mask_u,
    const float* __restrict__ mask_neg,
    float* __restrict__ out,
    int B, float neg_inv_B)
{
    const int lane = threadIdx.x & 31;
    const int warp_in_blk = threadIdx.x >> 5;
    const int b = blockIdx.x * WARPS_PER_BLOCK + warp_in_blk;

    const int sub = lane & 15;   // 16 lanes cover one 128-float row (8 floats each)
    const int grp = lane >> 4;   // half-warp id: neg iteration does k = 2*it+grp

    float warp_loss = 0.0f;

    if (b < B) {
        const int foff = sub * 8;

        // ---- hoist all neg indices first (independent of everything below) ----
        int nidx[K_NEG / 2];
        #pragma unroll
        for (int it = 0; it < K_NEG / 2; ++it)
            nidx[it] = neg_words[(size_t)b * K_NEG + 2 * it + grp];

        // ---- v = V_emb[ctx[b]] * mask_v[b] (duplicated across half-warps) ----
        const int c = ctx_words[b];
        float v[8], m[8];
        ldg256_keep(V_emb + (size_t)c * E_DIM + foff, v);
        ldg256_stream(mask_v + (size_t)b * E_DIM + foff, m);
        #pragma unroll
        for (int i = 0; i < 8; ++i) v[i] *= m[i];

        // ---- pos = dot(U_emb[tgt[b]] * mask_u[b], v)  (duplicated -> x2) ----
        const int t = target_words[b];
        float u[8];
        ldg256_keep(U_emb + (size_t)t * E_DIM + foff, u);
        ldg256_stream(mask_u + (size_t)b * E_DIM + foff, m);
        float pos = 0.0f;
        #pragma unroll
        for (int i = 0; i < 8; ++i) pos += u[i] * m[i] * v[i];

        // ---- negsum: 2 k's per iteration (one per half-warp), fully unrolled ----
        float negsum = 0.0f;
        #pragma unroll
        for (int it = 0; it < K_NEG / 2; ++it) {
            float un[8], mn[8];
            ldg256_keep(U_emb + (size_t)nidx[it] * E_DIM + foff, un);
            ldg256_stream(mask_neg + ((size_t)b * K_NEG + 2 * it + grp) * E_DIM + foff, mn);
            #pragma unroll
            for (int i = 0; i < 8; ++i) negsum += un[i] * mn[i] * v[i];
        }
        negsum = -negsum;

        // ---- warp reductions ----
        #pragma unroll
        for (int off = 16; off > 0; off >>= 1) {
            pos    += __shfl_xor_sync(0xFFFFFFFFu, pos, off);
            negsum += __shfl_xor_sync(0xFFFFFFFFu, negsum, off);
        }
        pos *= 0.5f;  // pos dot was computed by both half-warps

        if (lane == 0)
            warp_loss = (log_sigmoid(pos) + log_sigmoid(negsum)) * neg_inv_B;
    }

    // ---- block reduction, one atomic per block ----
    __shared__ float sm[WARPS_PER_BLOCK];
    if (lane == 0) sm[warp_in_blk] = warp_loss;
    __syncthreads();
    if (threadIdx.x == 0) {
        float s = 0.0f;
        #pragma unroll
        for (int i = 0; i < WARPS_PER_BLOCK; ++i) s += sm[i];
        atomicAdd(out, s);
    }
}

extern "C" void kernel_launch(void* const* d_in, const int* in_sizes, int n_in,
                              void* d_out, int out_size)
{
    const int*   ctx      = (const int*)  d_in[0];
    const int*   tgt      = (const int*)  d_in[1];
    const int*   neg      = (const int*)  d_in[2];
    const float* V_emb    = (const float*)d_in[3];
    const float* U_emb    = (const float*)d_in[4];
    const float* mask_v   = (const float*)d_in[5];
    const float* mask_u   = (const float*)d_in[6];
    const float* mask_neg = (const float*)d_in[7];
    float* out = (float*)d_out;

    const int B = in_sizes[0];
    const float neg_inv_B = -1.0f / (float)B;

    cbow_zero<<<1, 32>>>(out);

    const int blocks = (B + WARPS_PER_BLOCK - 1) / WARPS_PER_BLOCK;
    cbow_loss_kernel<<<blocks, THREADS>>>(
        ctx, tgt, neg, V_emb, U_emb, mask_v, mask_u, mask_neg,
        out, B, neg_inv_B);
}

// round 8
// speedup vs baseline: 1.3137x; 1.0204x over previous
#include <cuda_runtime.h>
#include <cuda_bf16.h>
#include <cstdint>

// CBOW negative-sampling loss.
// Inputs (metadata order):
//  0: ctx_words    int32  [B,1]
//  1: target_words int32  [B,1]
//  2: neg_words    int32  [B,K]
//  3: V_emb        f32    [VOCAB,E]
//  4: U_emb        f32    [VOCAB,E]
//  5: mask_v       f32    [B,1,E]
//  6: mask_u       f32    [B,1,E]
//  7: mask_neg     f32    [B,K,E]
// Output: scalar f32 = -mean_b( logsig(pos_b) + logsig(negsum_b) )
//
// R7: L2 policy split by reuse. U table (7.2x reuse/run, 51.2MB) is the
//     ONLY evict_last set -> guaranteed L2 residency. V table (0.65x
//     reuse) demoted to stream class (evict_first) alongside the masks.
//     Previous config protected U+V = 102MB in a 126MB L2 and thrashed
//     its own protected set (~90MB/run gather misses).

#define E_DIM 128
#define K_NEG 10
#define THREADS 256
#define WARPS_PER_BLOCK (THREADS / 32)

__device__ __forceinline__ float log_sigmoid(float x) {
    return fminf(x, 0.0f) - log1pf(expf(-fabsf(x)));
}

// 256-bit gather load, L2-resident class (U table only).
__device__ __forceinline__ void ldg256_keep(const float* p, float r[8]) {
    asm("ld.global.nc.L2::evict_last.v8.b32 {%0,%1,%2,%3,%4,%5,%6,%7}, [%8];"
        : "=f"(r[0]), "=f"(r[1]), "=f"(r[2]), "=f"(r[3]),
          "=f"(r[4]), "=f"(r[5]), "=f"(r[6]), "=f"(r[7])
        : "l"(p));
}

// 256-bit streaming load (masks + V gathers): evict first.
__device__ __forceinline__ void ldg256_stream(const float* p, float r[8]) {
    asm("ld.global.nc.L2::evict_first.v8.b32 {%0,%1,%2,%3,%4,%5,%6,%7}, [%8];"
        : "=f"(r[0]), "=f"(r[1]), "=f"(r[2]), "=f"(r[3]),
          "=f"(r[4]), "=f"(r[5]), "=f"(r[6]), "=f"(r[7])
        : "l"(p));
}

__global__ void __launch_bounds__(32) cbow_zero(float* out) {
    if (threadIdx.x == 0) out[0] = 0.0f;
}

__global__ void __launch_bounds__(THREADS) cbow_loss_kernel(
    const int* __restrict__ ctx_words,
    const int* __restrict__ target_words,
    const int* __restrict__ neg_words,
    const float* __restrict__ V_emb,
    const float* __restrict__ U_emb,
    const float* __restrict__ mask_v,
    const float* __restrict__ mask_u,
    const float* __restrict__ mask_neg,
    float* __restrict__ out,
    int B, float neg_inv_B)
{
    const int lane = threadIdx.x & 31;
    const int warp_in_blk = threadIdx.x >> 5;
    const int b = blockIdx.x * WARPS_PER_BLOCK + warp_in_blk;

    const int sub = lane & 15;   // 16 lanes cover one 128-float row (8 floats each)
    const int grp = lane >> 4;   // half-warp id: neg iteration does k = 2*it+grp

    float warp_loss = 0.0f;

    if (b < B) {
        const int foff = sub * 8;

        // ---- hoist all neg indices (independent of everything below) ----
        int nidx[K_NEG / 2];
        #pragma unroll
        for (int it = 0; it < K_NEG / 2; ++it)
            nidx[it] = neg_words[(size_t)b * K_NEG + 2 * it + grp];

        // ---- v = V_emb[ctx[b]] * mask_v[b]  (V gather = stream class) ----
        const int c = ctx_words[b];
        float v[8], m[8];
        ldg256_stream(V_emb + (size_t)c * E_DIM + foff, v);
        ldg256_stream(mask_v + (size_t)b * E_DIM + foff, m);
        #pragma unroll
        for (int i = 0; i < 8; ++i) v[i] *= m[i];

        // ---- pos = dot(U_emb[tgt[b]] * mask_u[b], v)  (duplicated -> x2) ----
        const int t = target_words[b];
        float u[8];
        ldg256_keep(U_emb + (size_t)t * E_DIM + foff, u);
        ldg256_stream(mask_u + (size_t)b * E_DIM + foff, m);
        float pos = 0.0f;
        #pragma unroll
        for (int i = 0; i < 8; ++i) pos += u[i] * m[i] * v[i];

        // ---- negsum: 2 k's per iteration (one per half-warp), unrolled ----
        float negsum = 0.0f;
        #pragma unroll
        for (int it = 0; it < K_NEG / 2; ++it) {
            float un[8], mn[8];
            ldg256_keep(U_emb + (size_t)nidx[it] * E_DIM + foff, un);
            ldg256_stream(mask_neg + ((size_t)b * K_NEG + 2 * it + grp) * E_DIM + foff, mn);
            #pragma unroll
            for (int i = 0; i < 8; ++i) negsum += un[i] * mn[i] * v[i];
        }
        negsum = -negsum;

        // ---- warp reductions ----
        #pragma unroll
        for (int off = 16; off > 0; off >>= 1) {
            pos    += __shfl_xor_sync(0xFFFFFFFFu, pos, off);
            negsum += __shfl_xor_sync(0xFFFFFFFFu, negsum, off);
        }
        pos *= 0.5f;  // pos dot was computed by both half-warps

        if (lane == 0)
            warp_loss = (log_sigmoid(pos) + log_sigmoid(negsum)) * neg_inv_B;
    }

    // ---- block reduction, one atomic per block ----
    __shared__ float sm[WARPS_PER_BLOCK];
    if (lane == 0) sm[warp_in_blk] = warp_loss;
    __syncthreads();
    if (threadIdx.x == 0) {
        float s = 0.0f;
        #pragma unroll
        for (int i = 0; i < WARPS_PER_BLOCK; ++i) s += sm[i];
        atomicAdd(out, s);
    }
}

extern "C" void kernel_launch(void* const* d_in, const int* in_sizes, int n_in,
                              void* d_out, int out_size)
{
    const int*   ctx      = (const int*)  d_in[0];
    const int*   tgt      = (const int*)  d_in[1];
    const int*   neg      = (const int*)  d_in[2];
    const float* V_emb    = (const float*)d_in[3];
    const float* U_emb    = (const float*)d_in[4];
    const float* mask_v   = (const float*)d_in[5];
    const float* mask_u   = (const float*)d_in[6];
    const float* mask_neg = (const float*)d_in[7];
    float* out = (float*)d_out;

    const int B = in_sizes[0];
    const float neg_inv_B = -1.0f / (float)B;

    cbow_zero<<<1, 32>>>(out);

    const int blocks = (B + WARPS_PER_BLOCK - 1) / WARPS_PER_BLOCK;
    cbow_loss_kernel<<<blocks, THREADS>>>(
        ctx, tgt, neg, V_emb, U_emb, mask_v, mask_u, mask_neg,
        out, B, neg_inv_B);
}